// round 10
// baseline (speedup 1.0000x reference)
#include <cuda_runtime.h>
#include <cstdint>
#define NN 20000
#define EE 320000
using u64 = unsigned long long;

__device__ float g_x[NN*3];
__device__ float g_h[NN*64];
__device__ float g_A[NN*64];
__device__ float g_B[NN*64];
__device__ float g_agg[NN*64];
__device__ float g_xacc[NN*3];
__device__ float g_cnt[NN];
__device__ float g_invc[NN];

__device__ __forceinline__ float silu(float v){ return __fdividef(v,1.f+__expf(-v)); }
__device__ __forceinline__ u64 mk2(float a,float b){u64 r;asm("mov.b64 %0,{%1,%2};":"=l"(r):"f"(a),"f"(b));return r;}
__device__ __forceinline__ u64 pk2(float a){u64 r;asm("mov.b64 %0,{%1,%1};":"=l"(r):"f"(a));return r;}
__device__ __forceinline__ u64 ffma2(u64 a,u64 b,u64 c){u64 d;asm("fma.rn.f32x2 %0,%1,%2,%3;":"=l"(d):"l"(a),"l"(b),"l"(c));return d;}
__device__ __forceinline__ float2 up2(u64 a){float x,y;asm("mov.b64 {%0,%1},%2;":"=f"(x),"=f"(y):"l"(a));return make_float2(x,y);}
__device__ __forceinline__ float fin(u64 a){float2 v=up2(a);return v.x+v.y;}

// ---- node-side scalar machinery (validated R4/R7/R9) ----
__device__ __forceinline__ void stageW(u64* dst,const float* __restrict__ src,int K,int tid,int nthr){
  int tot=(K/2)*64;
  for(int i=tid;i<tot;i+=nthr){
    int kp=i>>6,c=i&63;
    u64 v=mk2(src[(2*kp)*64+c],src[(2*kp+1)*64+c]);
    dst[(kp<<6)+((c&2)?32:0)+((c>>2)<<1)+(c&1)]=v;
  }
}
__device__ __forceinline__ void ainit(u64* acc,const float* b4,int q){
  float4 b=*(const float4*)&b4[q*4];
#pragma unroll
  for(int r=0;r<4;r++){
    acc[4*r]=mk2(b.x,0.f); acc[4*r+1]=mk2(b.y,0.f);
    acc[4*r+2]=mk2(b.z,0.f); acc[4*r+3]=mk2(b.w,0.f);
  }
}
__device__ __forceinline__ void a0init(u64* acc){
#pragma unroll
  for(int i=0;i<16;i++) acc[i]=0ull;
}
template<int K>
__device__ __forceinline__ void mv8p(const float* vb,int ST,const u64* Wp,int q,u64* acc){
#pragma unroll 8
  for(int kp=0;kp<K/2;kp+=2){
    ulonglong2 a0=*(const ulonglong2*)(vb+2*kp);
    ulonglong2 a1=*(const ulonglong2*)(vb+ST+2*kp);
    ulonglong2 a2=*(const ulonglong2*)(vb+2*ST+2*kp);
    ulonglong2 a3=*(const ulonglong2*)(vb+3*ST+2*kp);
    const u64* wr=Wp+(kp<<6)+2*q;
    ulonglong2 wa0=*(const ulonglong2*)wr;
    ulonglong2 wb0=*(const ulonglong2*)(wr+32);
    ulonglong2 wa1=*(const ulonglong2*)(wr+64);
    ulonglong2 wb1=*(const ulonglong2*)(wr+96);
#define RSTEP(r,A) \
    acc[4*r+0]=ffma2(A.x,wa0.x,acc[4*r+0]); acc[4*r+1]=ffma2(A.x,wa0.y,acc[4*r+1]); \
    acc[4*r+2]=ffma2(A.x,wb0.x,acc[4*r+2]); acc[4*r+3]=ffma2(A.x,wb0.y,acc[4*r+3]); \
    acc[4*r+0]=ffma2(A.y,wa1.x,acc[4*r+0]); acc[4*r+1]=ffma2(A.y,wa1.y,acc[4*r+1]); \
    acc[4*r+2]=ffma2(A.y,wb1.x,acc[4*r+2]); acc[4*r+3]=ffma2(A.y,wb1.y,acc[4*r+3]);
    RSTEP(0,a0) RSTEP(1,a1) RSTEP(2,a2) RSTEP(3,a3)
#undef RSTEP
  }
}

__global__ void k_zero(){
  int i=blockIdx.x*blockDim.x+threadIdx.x;
  if(i<NN) g_cnt[i]=0.f;
  if(i<NN*3) g_xacc[i]=0.f;
}
__global__ void k_count(const int* __restrict__ erow){
  int e=blockIdx.x*blockDim.x+threadIdx.x;
  if(e<EE) atomicAdd(&g_cnt[erow[e]],1.f);
}

// h0=h16@Wi+bi ; A=h0@EA+eb ; B=h0@EB ; init x, invc, agg=0  (validated)
__global__ void __launch_bounds__(256) k_embed(
    const float* __restrict__ h16,const float* __restrict__ xin,
    const float* __restrict__ Wi,const float* __restrict__ bi,
    const float* __restrict__ EA,const float* __restrict__ eb,
    const float* __restrict__ EB){
  extern __shared__ char sr[];
  u64* sWip=(u64*)sr; u64* sEAp=(u64*)(sr+4096); u64* sEBp=(u64*)(sr+20480);
  float* sbi=(float*)(sr+36864); float* seb=(float*)(sr+37120);
  float* vbase=(float*)(sr+37376);
  const int tid=threadIdx.x,wid=tid>>5,lane=tid&31,q=lane&15,g2=lane>>4;
  stageW(sWip,Wi,16,tid,256);
  stageW(sEAp,EA,64,tid,256);
  stageW(sEBp,EB,64,tid,256);
  if(tid<64){sbi[tid]=bi[tid];seb[tid]=eb[tid];}
  float* vb=vbase+wid*(8*84);
  int nbase=blockIdx.x*64+wid*8;
#pragma unroll
  for(int t=0;t<4;t++){
    int e=t*2+g2,n=nbase+e;
    if(q<4){
      float4 v=make_float4(0,0,0,0);
      if(n<NN) v=*(const float4*)&h16[n*16+q*4];
      *(float4*)&vb[e*84+q*4]=v;
    }
    if(n<NN) *(float4*)&g_agg[n*64+q*4]=make_float4(0,0,0,0);
  }
  if(lane<8){int n=nbase+lane; if(n<NN) g_invc[n]=__fdividef(1.f,fmaxf(g_cnt[n],1.f));}
  if(lane<24){int e=lane/3,d=lane-3*(lane/3),n=nbase+e; if(n<NN) g_x[n*3+d]=xin[n*3+d];}
  __syncthreads();
  u64 acc[16];
  ainit(acc,sbi,q);
  mv8p<16>(vb+g2*4*84,84,sWip,q,acc);
  __syncwarp();
#pragma unroll
  for(int r=0;r<4;r++){
    int e=g2*4+r,n=nbase+e;
    float4 h0=make_float4(fin(acc[4*r]),fin(acc[4*r+1]),fin(acc[4*r+2]),fin(acc[4*r+3]));
    *(float4*)&vb[e*84+16+q*4]=h0;
    if(n<NN) *(float4*)&g_h[n*64+q*4]=h0;
  }
  __syncwarp();
  ainit(acc,seb,q);
  mv8p<64>(vb+g2*4*84+16,84,sEAp,q,acc);
#pragma unroll
  for(int r=0;r<4;r++){
    int n=nbase+g2*4+r;
    if(n<NN) *(float4*)&g_A[n*64+q*4]=make_float4(fin(acc[4*r]),fin(acc[4*r+1]),fin(acc[4*r+2]),fin(acc[4*r+3]));
  }
  a0init(acc);
  mv8p<64>(vb+g2*4*84+16,84,sEBp,q,acc);
#pragma unroll
  for(int r=0;r<4;r++){
    int n=nbase+g2*4+r;
    if(n<NN) *(float4*)&g_B[n*64+q*4]=make_float4(fin(acc[4*r]),fin(acc[4*r+1]),fin(acc[4*r+2]),fin(acc[4*r+3]));
  }
}

// ---- edge kernel: CTA-level SGEMM, 128 edges/CTA, fp32 ----
// smem floats: sW1 0 (64x68), sC1 4352 (64x68), sb 8704 (256),
// ST 8960 (union: transposed 64x132 / row-major 128x68 = 8704),
// meta 17664: dfb 384, rad 128, icb 128, rw 128, cl 128, phi 128. total 18688 fl.
__global__ void __launch_bounds__(256,2) k_edge(
    const int* __restrict__ erow,const int* __restrict__ ecol,
    const float* __restrict__ w1c,const float* __restrict__ W2,
    const float* __restrict__ b2,const float* __restrict__ CW1,
    const float* __restrict__ cb1,const float* __restrict__ cw2){
  extern __shared__ float sf[];
  float* sW1=sf; float* sC1=sf+4352; float* sb=sf+8704; float* ST=sf+8960;
  float* dfb=sf+17664; float* rad=sf+18048; float* icb=sf+18176;
  int* rw=(int*)(sf+18304); int* cl=(int*)(sf+18432); float* phiS=sf+18560;
  const int tid=threadIdx.x,lane=tid&31;
  for(int idx=tid;idx<4096;idx+=256){
    int k=idx>>6,c=idx&63;
    sW1[k*68+c]=W2[idx]; sC1[k*68+c]=CW1[idx];
  }
  if(tid<64){ sb[tid]=w1c[tid]; sb[64+tid]=b2[tid]; sb[128+tid]=cb1[tid]; sb[192+tid]=cw2[tid]; }
  if(tid<128){
    int e=blockIdx.x*128+tid;
    int r=erow[e],c=ecol[e];
    rw[tid]=r; cl[tid]=c;
    float dx=g_x[r*3]-g_x[c*3],dy=g_x[r*3+1]-g_x[c*3+1],dz=g_x[r*3+2]-g_x[c*3+2];
    dfb[tid*3]=dx; dfb[tid*3+1]=dy; dfb[tid*3+2]=dz;
    rad[tid]=dx*dx+dy*dy+dz*dz; icb[tid]=g_invc[r];
  }
  __syncthreads();
  // phase1: m1 = silu(A[r]+B[c]+rad*w1c) -> ST transposed [k][e], stride 132
  {
    int e=tid&127, half=tid>>7;
    int r=rw[e], c=cl[e]; float rd=rad[e];
#pragma unroll
    for(int o=0;o<8;o++){
      int kb=half*32+o*4;
      float4 a4=*(const float4*)&g_A[r*64+kb];
      float4 b4=*(const float4*)&g_B[c*64+kb];
      float4 w4=*(const float4*)&sb[kb];
      ST[(kb+0)*132+e]=silu(a4.x+b4.x+rd*w4.x);
      ST[(kb+1)*132+e]=silu(a4.y+b4.y+rd*w4.y);
      ST[(kb+2)*132+e]=silu(a4.z+b4.z+rd*w4.z);
      ST[(kb+3)*132+e]=silu(a4.w+b4.w+rd*w4.w);
    }
  }
  __syncthreads();
  const int ii=tid>>4, jj=tid&15;   // 8 edges rows 8*ii.., 4 cols 4*jj..
  // ---- matvec1: C = ST^T @ W2 ; acc2[rp][c] = (out[2rp][c],out[2rp+1][c]) ----
  u64 acc2[4][4];
#pragma unroll
  for(int a=0;a<4;a++){acc2[a][0]=0;acc2[a][1]=0;acc2[a][2]=0;acc2[a][3]=0;}
#pragma unroll 4
  for(int k=0;k<64;k++){
    const u64* ap=(const u64*)&ST[k*132+8*ii];
    u64 a0=ap[0],a1=ap[1],a2=ap[2],a3=ap[3];
    float4 b4=*(const float4*)&sW1[k*68+4*jj];
    u64 s0=pk2(b4.x),s1=pk2(b4.y),s2=pk2(b4.z),s3=pk2(b4.w);
#define MST(rp,A) \
    acc2[rp][0]=ffma2(A,s0,acc2[rp][0]); acc2[rp][1]=ffma2(A,s1,acc2[rp][1]); \
    acc2[rp][2]=ffma2(A,s2,acc2[rp][2]); acc2[rp][3]=ffma2(A,s3,acc2[rp][3]);
    MST(0,a0) MST(1,a1) MST(2,a2) MST(3,a3)
#undef MST
  }
  __syncthreads();   // ST dead; safe to overwrite as mROW
  // epilogue1: m = silu(C+b2); red into agg; store mROW[e][68]
  {
    float4 bb=*(const float4*)&sb[64+4*jj];
#pragma unroll
    for(int rp=0;rp<4;rp++){
      float2 v0=up2(acc2[rp][0]),v1=up2(acc2[rp][1]),v2=up2(acc2[rp][2]),v3=up2(acc2[rp][3]);
      float4 mA=make_float4(silu(v0.x+bb.x),silu(v1.x+bb.y),silu(v2.x+bb.z),silu(v3.x+bb.w));
      float4 mB=make_float4(silu(v0.y+bb.x),silu(v1.y+bb.y),silu(v2.y+bb.z),silu(v3.y+bb.w));
      int eA=8*ii+2*rp, eB=eA+1;
      asm volatile("red.global.add.v4.f32 [%0],{%1,%2,%3,%4};"
        ::"l"(&g_agg[rw[eA]*64+4*jj]),"f"(mA.x),"f"(mA.y),"f"(mA.z),"f"(mA.w):"memory");
      asm volatile("red.global.add.v4.f32 [%0],{%1,%2,%3,%4};"
        ::"l"(&g_agg[rw[eB]*64+4*jj]),"f"(mB.x),"f"(mB.y),"f"(mB.z),"f"(mB.w):"memory");
      *(float4*)&ST[eA*68+4*jj]=mA;
      *(float4*)&ST[eB*68+4*jj]=mB;
    }
  }
  __syncthreads();
  // ---- matvec2: T = mROW @ CW1 ; split-k acc: ak[r][c] = (even,odd) ----
  u64 ak[8][4];
#pragma unroll
  for(int r=0;r<8;r++){ak[r][0]=0;ak[r][1]=0;ak[r][2]=0;ak[r][3]=0;}
#pragma unroll 4
  for(int k2=0;k2<32;k2++){
    u64 a64[8];
#pragma unroll
    for(int r=0;r<8;r++) a64[r]=*(const u64*)&ST[(8*ii+r)*68+2*k2];
    float4 bA=*(const float4*)&sC1[(2*k2)*68+4*jj];
    float4 bB=*(const float4*)&sC1[(2*k2+1)*68+4*jj];
    u64 kb0=mk2(bA.x,bB.x),kb1=mk2(bA.y,bB.y),kb2=mk2(bA.z,bB.z),kb3=mk2(bA.w,bB.w);
#pragma unroll
    for(int r=0;r<8;r++){
      ak[r][0]=ffma2(a64[r],kb0,ak[r][0]);
      ak[r][1]=ffma2(a64[r],kb1,ak[r][1]);
      ak[r][2]=ffma2(a64[r],kb2,ak[r][2]);
      ak[r][3]=ffma2(a64[r],kb3,ak[r][3]);
    }
  }
  // epilogue2: phi = sum_c silu(T+cb1)*cw2 ; shfl-reduce over jj
  {
    float4 cb=*(const float4*)&sb[128+4*jj];
    float4 cw=*(const float4*)&sb[192+4*jj];
    float p[8];
#pragma unroll
    for(int r=0;r<8;r++){
      p[r]=silu(fin(ak[r][0])+cb.x)*cw.x+silu(fin(ak[r][1])+cb.y)*cw.y
          +silu(fin(ak[r][2])+cb.z)*cw.z+silu(fin(ak[r][3])+cb.w)*cw.w;
    }
#pragma unroll
    for(int off=1;off<16;off<<=1){
#pragma unroll
      for(int r=0;r<8;r++) p[r]+=__shfl_xor_sync(0xffffffffu,p[r],off);
    }
    if((lane&15)==0){
#pragma unroll
      for(int r=0;r<8;r++) phiS[8*ii+r]=p[r];
    }
  }
  __syncthreads();
  if(tid<128){
    float s=phiS[tid]*icb[tid];
    int r=rw[tid];
    atomicAdd(&g_xacc[r*3+0],dfb[tid*3+0]*s);
    atomicAdd(&g_xacc[r*3+1],dfb[tid*3+1]*s);
    atomicAdd(&g_xacc[r*3+2],dfb[tid*3+2]*s);
  }
}

// node: x+=xacc; t=silu([h|agg]@NW1+nb1); h+=t@NW2+nb2; next-layer A/B or final out (validated)
__global__ void __launch_bounds__(256) k_node(
    const float* __restrict__ NW1,const float* __restrict__ nb1,
    const float* __restrict__ NW2,const float* __restrict__ nb2,
    const float* __restrict__ WA,const float* __restrict__ ba,
    const float* __restrict__ WB,int last,float* __restrict__ outp){
  extern __shared__ char sr[];
  u64* sN1p=(u64*)sr;
  u64* sN2p=(u64*)(sr+32768);
  u64* sAp =(u64*)(sr+49152);
  float* snb1=(float*)(sr+65536); float* snb2=(float*)(sr+65792);
  float* sba=(float*)(sr+66048);
  float* vbase=(float*)(sr+66304);
  const int tid=threadIdx.x,wid=tid>>5,lane=tid&31,q=lane&15,g2=lane>>4;
  stageW(sN1p,NW1,128,tid,256);
  stageW(sN2p,NW2,64,tid,256);
  stageW(sAp,WA,64,tid,256);
  if(tid<64){snb1[tid]=nb1[tid];snb2[tid]=nb2[tid];sba[tid]=ba[tid];}
  float* vb=vbase+wid*1056;
  int nbase=blockIdx.x*64+wid*8;
#pragma unroll
  for(int t=0;t<4;t++){
    int e=t*2+g2,n=nbase+e;
    float4 h4=make_float4(0,0,0,0),a4=make_float4(0,0,0,0);
    if(n<NN){
      h4=*(const float4*)&g_h[n*64+q*4];
      a4=*(const float4*)&g_agg[n*64+q*4];
      *(float4*)&g_agg[n*64+q*4]=make_float4(0,0,0,0);
    }
    *(float4*)&vb[e*132+q*4]=h4;
    *(float4*)&vb[e*132+64+q*4]=a4;
  }
  if(lane<24){
    int e=lane/3,d=lane-3*(lane/3),n=nbase+e;
    if(n<NN){
      float nx=g_x[n*3+d]+g_xacc[n*3+d];
      g_x[n*3+d]=nx; g_xacc[n*3+d]=0.f;
      if(last) outp[NN*64+n*3+d]=nx;
    }
  }
  __syncthreads();
  u64 acc[16];
  ainit(acc,snb1,q);
  mv8p<128>(vb+g2*4*132,132,sN1p,q,acc);
  __syncwarp();
#pragma unroll
  for(int r=0;r<4;r++){
    int e=g2*4+r;
    *(float4*)&vb[e*132+64+q*4]=make_float4(
      silu(fin(acc[4*r])),silu(fin(acc[4*r+1])),silu(fin(acc[4*r+2])),silu(fin(acc[4*r+3])));
  }
  __syncthreads();
  if(!last) stageW(sN1p,WB,64,tid,256);
  ainit(acc,snb2,q);
  mv8p<64>(vb+g2*4*132+64,132,sN2p,q,acc);
  __syncwarp();
#pragma unroll
  for(int r=0;r<4;r++){
    int e=g2*4+r,n=nbase+e;
    float4 ho=*(const float4*)&vb[e*132+q*4];
    float4 hn=make_float4(ho.x+fin(acc[4*r]),ho.y+fin(acc[4*r+1]),
                          ho.z+fin(acc[4*r+2]),ho.w+fin(acc[4*r+3]));
    *(float4*)&vb[e*132+q*4]=hn;
    if(n<NN) *(float4*)&g_h[n*64+q*4]=hn;
  }
  __syncthreads();
  ainit(acc,sba,q);
  mv8p<64>(vb+g2*4*132,132,sAp,q,acc);
  if(last){
#pragma unroll
    for(int r=0;r<4;r++){
      int n=nbase+g2*4+r;
      if(n<NN) *(float4*)&outp[n*64+q*4]=make_float4(fin(acc[4*r]),fin(acc[4*r+1]),fin(acc[4*r+2]),fin(acc[4*r+3]));
    }
  } else {
#pragma unroll
    for(int r=0;r<4;r++){
      int n=nbase+g2*4+r;
      if(n<NN) *(float4*)&g_A[n*64+q*4]=make_float4(fin(acc[4*r]),fin(acc[4*r+1]),fin(acc[4*r+2]),fin(acc[4*r+3]));
    }
    a0init(acc);
    mv8p<64>(vb+g2*4*132,132,sN1p,q,acc);
#pragma unroll
    for(int r=0;r<4;r++){
      int n=nbase+g2*4+r;
      if(n<NN) *(float4*)&g_B[n*64+q*4]=make_float4(fin(acc[4*r]),fin(acc[4*r+1]),fin(acc[4*r+2]),fin(acc[4*r+3]));
    }
  }
}

extern "C" void kernel_launch(void* const* d_in,const int* in_sizes,int n_in,
                              void* d_out,int out_size){
  const float* h16=(const float*)d_in[0];
  const float* xin=(const float*)d_in[1];
  const int*   ei =(const int*  )d_in[2];
  const float* Wi =(const float*)d_in[3];
  const float* bi =(const float*)d_in[4];
  const float* ew1=(const float*)d_in[5];
  const float* eb1=(const float*)d_in[6];
  const float* ew2=(const float*)d_in[7];
  const float* eb2=(const float*)d_in[8];
  const float* cw1=(const float*)d_in[9];
  const float* cb1=(const float*)d_in[10];
  const float* cw2=(const float*)d_in[11];
  const float* nw1=(const float*)d_in[12];
  const float* nb1=(const float*)d_in[13];
  const float* nw2=(const float*)d_in[14];
  const float* nb2=(const float*)d_in[15];
  const float* Wo =(const float*)d_in[16];
  const float* bo =(const float*)d_in[17];
  float* outp=(float*)d_out;
  const int* erow=ei; const int* ecol=ei+EE;

  const int SME=58880, SMEDGE=18688*4, SMN=100096;
  cudaFuncSetAttribute(k_embed,cudaFuncAttributeMaxDynamicSharedMemorySize,SME);
  cudaFuncSetAttribute(k_edge, cudaFuncAttributeMaxDynamicSharedMemorySize,SMEDGE);
  cudaFuncSetAttribute(k_node, cudaFuncAttributeMaxDynamicSharedMemorySize,SMN);

  const int NB=(NN+63)/64;
  k_zero<<<(NN*3+255)/256,256>>>();
  k_count<<<(EE+255)/256,256>>>(erow);
  k_embed<<<NB,256,SME>>>(h16,xin,Wi,bi,ew1,eb1,ew1+64*64);
  for(int l=0;l<4;l++){
    k_edge<<<EE/128,256,SMEDGE>>>(erow,ecol,ew1+l*129*64+128*64,ew2+l*4096,eb2+l*64,
                                  cw1+l*4096,cb1+l*64,cw2+l*64);
    int last=(l==3);
    const float* WA = last ? Wo : ew1+(l+1)*129*64;
    const float* ba = last ? bo : eb1+(l+1)*64;
    const float* WB = last ? Wo : WA+64*64;
    k_node<<<NB,256,SMN>>>(nw1+l*128*64,nb1+l*64,nw2+l*4096,nb2+l*64,WA,ba,WB,last,outp);
  }
}

// round 11
// speedup vs baseline: 1.3323x; 1.3323x over previous
#include <cuda_runtime.h>
#include <cstdint>
#define NN 20000
#define EE 320000
using u64 = unsigned long long;

__device__ float g_x[NN*3];
__device__ float g_h[NN*64];
__device__ float g_A[NN*64];
__device__ float g_B[NN*64];
__device__ float g_agg[NN*64];
__device__ float g_xacc[NN*3];
__device__ float g_cnt[NN];
__device__ float g_invc[NN];

__device__ __forceinline__ float silu(float v){ return __fdividef(v,1.f+__expf(-v)); }
__device__ __forceinline__ u64 mk2(float a,float b){u64 r;asm("mov.b64 %0,{%1,%2};":"=l"(r):"f"(a),"f"(b));return r;}
__device__ __forceinline__ u64 pack2(float x){u64 r;asm("mov.b64 %0,{%1,%1};":"=l"(r):"f"(x));return r;}
__device__ __forceinline__ u64 ffma2(u64 a,u64 b,u64 c){u64 d;asm("fma.rn.f32x2 %0,%1,%2,%3;":"=l"(d):"l"(a),"l"(b),"l"(c));return d;}
__device__ __forceinline__ float2 unpk(u64 a){float x,y;asm("mov.b64 {%0,%1},%2;":"=f"(x),"=f"(y):"l"(a));return make_float2(x,y);}
__device__ __forceinline__ float fin(u64 a){float2 v=unpk(a);return v.x+v.y;}

// ======== R3-validated edge matvec: 8 rows x W[K,64], row-major weights ========
// q=lane&15 -> out cols [4q,4q+4), g2=lane>>4 -> rows g2*4..g2*4+3.
// acc[2r]=cols(4q,4q+1), acc[2r+1]=cols(4q+2,4q+3) of row r.
template<int K>
__device__ __forceinline__ void mv8(const float* vb,int ST,const float* W,int q,u64* acc){
#pragma unroll 4
  for(int k4=0;k4<K;k4+=4){
    float4 a0=*(const float4*)(vb+0*ST+k4);
    float4 a1=*(const float4*)(vb+1*ST+k4);
    float4 a2=*(const float4*)(vb+2*ST+k4);
    float4 a3=*(const float4*)(vb+3*ST+k4);
    float va[4][4]={{a0.x,a0.y,a0.z,a0.w},{a1.x,a1.y,a1.z,a1.w},
                    {a2.x,a2.y,a2.z,a2.w},{a3.x,a3.y,a3.z,a3.w}};
#pragma unroll
    for(int j=0;j<4;j++){
      ulonglong2 w=*(const ulonglong2*)(W+(k4+j)*64+q*4);
#pragma unroll
      for(int r=0;r<4;r++){
        u64 p=pack2(va[r][j]);
        acc[2*r]  =ffma2(w.x,p,acc[2*r]);
        acc[2*r+1]=ffma2(w.y,p,acc[2*r+1]);
      }
    }
  }
}
__device__ __forceinline__ void acc_init8(u64* acc,const float* sb,int q){
  u64 b01=((const u64*)sb)[q*2], b23=((const u64*)sb)[q*2+1];
#pragma unroll
  for(int r=0;r<4;r++){ acc[2*r]=b01; acc[2*r+1]=b23; }
}

// ======== node-side scalar machinery (validated R4/R7/R9) ========
__device__ __forceinline__ void stageW(u64* dst,const float* __restrict__ src,int K,int tid,int nthr){
  int tot=(K/2)*64;
  for(int i=tid;i<tot;i+=nthr){
    int kp=i>>6,c=i&63;
    u64 v=mk2(src[(2*kp)*64+c],src[(2*kp+1)*64+c]);
    dst[(kp<<6)+((c&2)?32:0)+((c>>2)<<1)+(c&1)]=v;
  }
}
__device__ __forceinline__ void ainit(u64* acc,const float* b4,int q){
  float4 b=*(const float4*)&b4[q*4];
#pragma unroll
  for(int r=0;r<4;r++){
    acc[4*r]=mk2(b.x,0.f); acc[4*r+1]=mk2(b.y,0.f);
    acc[4*r+2]=mk2(b.z,0.f); acc[4*r+3]=mk2(b.w,0.f);
  }
}
__device__ __forceinline__ void a0init(u64* acc){
#pragma unroll
  for(int i=0;i<16;i++) acc[i]=0ull;
}
template<int K>
__device__ __forceinline__ void mv8p(const float* vb,int ST,const u64* Wp,int q,u64* acc){
#pragma unroll 8
  for(int kp=0;kp<K/2;kp+=2){
    ulonglong2 a0=*(const ulonglong2*)(vb+2*kp);
    ulonglong2 a1=*(const ulonglong2*)(vb+ST+2*kp);
    ulonglong2 a2=*(const ulonglong2*)(vb+2*ST+2*kp);
    ulonglong2 a3=*(const ulonglong2*)(vb+3*ST+2*kp);
    const u64* wr=Wp+(kp<<6)+2*q;
    ulonglong2 wa0=*(const ulonglong2*)wr;
    ulonglong2 wb0=*(const ulonglong2*)(wr+32);
    ulonglong2 wa1=*(const ulonglong2*)(wr+64);
    ulonglong2 wb1=*(const ulonglong2*)(wr+96);
#define RSTEP(r,A) \
    acc[4*r+0]=ffma2(A.x,wa0.x,acc[4*r+0]); acc[4*r+1]=ffma2(A.x,wa0.y,acc[4*r+1]); \
    acc[4*r+2]=ffma2(A.x,wb0.x,acc[4*r+2]); acc[4*r+3]=ffma2(A.x,wb0.y,acc[4*r+3]); \
    acc[4*r+0]=ffma2(A.y,wa1.x,acc[4*r+0]); acc[4*r+1]=ffma2(A.y,wa1.y,acc[4*r+1]); \
    acc[4*r+2]=ffma2(A.y,wb1.x,acc[4*r+2]); acc[4*r+3]=ffma2(A.y,wb1.y,acc[4*r+3]);
    RSTEP(0,a0) RSTEP(1,a1) RSTEP(2,a2) RSTEP(3,a3)
#undef RSTEP
  }
}

__global__ void k_zero(){
  int i=blockIdx.x*blockDim.x+threadIdx.x;
  if(i<NN) g_cnt[i]=0.f;
  if(i<NN*3) g_xacc[i]=0.f;
}
__global__ void k_count(const int* __restrict__ erow){
  int e=blockIdx.x*blockDim.x+threadIdx.x;
  if(e<EE) atomicAdd(&g_cnt[erow[e]],1.f);
}

// h0=h16@Wi+bi ; A=h0@EA+eb ; B=h0@EB ; init x, invc, agg=0  (validated R4/R7/R9)
__global__ void __launch_bounds__(256) k_embed(
    const float* __restrict__ h16,const float* __restrict__ xin,
    const float* __restrict__ Wi,const float* __restrict__ bi,
    const float* __restrict__ EA,const float* __restrict__ eb,
    const float* __restrict__ EB){
  extern __shared__ char sr[];
  u64* sWip=(u64*)sr; u64* sEAp=(u64*)(sr+4096); u64* sEBp=(u64*)(sr+20480);
  float* sbi=(float*)(sr+36864); float* seb=(float*)(sr+37120);
  float* vbase=(float*)(sr+37376);
  const int tid=threadIdx.x,wid=tid>>5,lane=tid&31,q=lane&15,g2=lane>>4;
  stageW(sWip,Wi,16,tid,256);
  stageW(sEAp,EA,64,tid,256);
  stageW(sEBp,EB,64,tid,256);
  if(tid<64){sbi[tid]=bi[tid];seb[tid]=eb[tid];}
  float* vb=vbase+wid*(8*84);
  int nbase=blockIdx.x*64+wid*8;
#pragma unroll
  for(int t=0;t<4;t++){
    int e=t*2+g2,n=nbase+e;
    if(q<4){
      float4 v=make_float4(0,0,0,0);
      if(n<NN) v=*(const float4*)&h16[n*16+q*4];
      *(float4*)&vb[e*84+q*4]=v;
    }
    if(n<NN) *(float4*)&g_agg[n*64+q*4]=make_float4(0,0,0,0);
  }
  if(lane<8){int n=nbase+lane; if(n<NN) g_invc[n]=__fdividef(1.f,fmaxf(g_cnt[n],1.f));}
  if(lane<24){int e=lane/3,d=lane-3*(lane/3),n=nbase+e; if(n<NN) g_x[n*3+d]=xin[n*3+d];}
  __syncthreads();
  u64 acc[16];
  ainit(acc,sbi,q);
  mv8p<16>(vb+g2*4*84,84,sWip,q,acc);
  __syncwarp();
#pragma unroll
  for(int r=0;r<4;r++){
    int e=g2*4+r,n=nbase+e;
    float4 h0=make_float4(fin(acc[4*r]),fin(acc[4*r+1]),fin(acc[4*r+2]),fin(acc[4*r+3]));
    *(float4*)&vb[e*84+16+q*4]=h0;
    if(n<NN) *(float4*)&g_h[n*64+q*4]=h0;
  }
  __syncwarp();
  ainit(acc,seb,q);
  mv8p<64>(vb+g2*4*84+16,84,sEAp,q,acc);
#pragma unroll
  for(int r=0;r<4;r++){
    int n=nbase+g2*4+r;
    if(n<NN) *(float4*)&g_A[n*64+q*4]=make_float4(fin(acc[4*r]),fin(acc[4*r+1]),fin(acc[4*r+2]),fin(acc[4*r+3]));
  }
  a0init(acc);
  mv8p<64>(vb+g2*4*84+16,84,sEBp,q,acc);
#pragma unroll
  for(int r=0;r<4;r++){
    int n=nbase+g2*4+r;
    if(n<NN) *(float4*)&g_B[n*64+q*4]=make_float4(fin(acc[4*r]),fin(acc[4*r+1]),fin(acc[4*r+2]),fin(acc[4*r+3]));
  }
}

// ======== edge kernel: 8 edges/warp, 64 edges/block (R3-validated, 757us run) ========
__global__ void __launch_bounds__(256,3) k_edge(
    const int* __restrict__ erow,const int* __restrict__ ecol,
    const float* __restrict__ w1c,const float* __restrict__ W2,
    const float* __restrict__ b2,const float* __restrict__ CW1,
    const float* __restrict__ cb1,const float* __restrict__ cw2){
  extern __shared__ char sr[];
  float* sW2=(float*)sr; float* sC1=(float*)(sr+16384);
  float* sw1c=(float*)(sr+32768); float* sb2=(float*)(sr+33024);
  float* scb1=(float*)(sr+33280); float* scw2=(float*)(sr+33536);
  float* wsmb=(float*)(sr+33792);
  const int tid=threadIdx.x,wid=tid>>5,lane=tid&31,q=lane&15,g2=lane>>4;
  for(int i=tid;i<1024;i+=256){((float4*)sW2)[i]=((const float4*)W2)[i];((float4*)sC1)[i]=((const float4*)CW1)[i];}
  if(tid<64){sw1c[tid]=w1c[tid];sb2[tid]=b2[tid];scb1[tid]=cb1[tid];scw2[tid]=cw2[tid];}
  float* wsm=wsmb+wid*1152;
  float* m1b=wsm; float* mb=wsm+544; float* dfb=wsm+1088;
  float* rdb=wsm+1112; float* icb=wsm+1120;
  int* rwb=(int*)(wsm+1128); int* clb=(int*)(wsm+1136);
  int ebase=blockIdx.x*64+wid*8;
  if(lane<8){
    int e=ebase+lane,r=erow[e],c=ecol[e];
    rwb[lane]=r; clb[lane]=c;
    float dx=g_x[r*3]-g_x[c*3],dy=g_x[r*3+1]-g_x[c*3+1],dz=g_x[r*3+2]-g_x[c*3+2];
    dfb[lane*3]=dx; dfb[lane*3+1]=dy; dfb[lane*3+2]=dz;
    rdb[lane]=dx*dx+dy*dy+dz*dz; icb[lane]=g_invc[r];
  }
  __syncthreads();
  { // m1 = silu(A[r]+B[c]+rad*w1c)
    float4 wc=*(const float4*)&sw1c[q*4];
#pragma unroll
    for(int t=0;t<4;t++){
      int e=t*2+g2;
      float4 av=*(const float4*)&g_A[rwb[e]*64+q*4];
      float4 bv=*(const float4*)&g_B[clb[e]*64+q*4];
      float rad=rdb[e];
      *(float4*)&m1b[e*68+q*4]=make_float4(
        silu(av.x+bv.x+rad*wc.x), silu(av.y+bv.y+rad*wc.y),
        silu(av.z+bv.z+rad*wc.z), silu(av.w+bv.w+rad*wc.w));
    }
  }
  __syncwarp();
  u64 acc[8];
  acc_init8(acc,sb2,q);
  mv8<64>(m1b+g2*4*68,68,sW2,q,acc);
#pragma unroll
  for(int r=0;r<4;r++){
    int e=g2*4+r;
    float2 lo=unpk(acc[2*r]),hi=unpk(acc[2*r+1]);
    float m0=silu(lo.x),m1=silu(lo.y),m2=silu(hi.x),m3=silu(hi.y);
    *(float4*)&mb[e*68+q*4]=make_float4(m0,m1,m2,m3);
    float* ap=&g_agg[rwb[e]*64+q*4];
    asm volatile("red.global.add.v4.f32 [%0],{%1,%2,%3,%4};"
                 ::"l"(ap),"f"(m0),"f"(m1),"f"(m2),"f"(m3):"memory");
  }
  __syncwarp();
  acc_init8(acc,scb1,q);
  mv8<64>(mb+g2*4*68,68,sC1,q,acc);
  float4 c4=*(const float4*)&scw2[q*4];
  float s[4];
#pragma unroll
  for(int r=0;r<4;r++){
    float2 lo=unpk(acc[2*r]),hi=unpk(acc[2*r+1]);
    s[r]=silu(lo.x)*c4.x+silu(lo.y)*c4.y+silu(hi.x)*c4.z+silu(hi.y)*c4.w;
  }
#pragma unroll
  for(int off=1;off<16;off<<=1){
#pragma unroll
    for(int r=0;r<4;r++) s[r]+=__shfl_xor_sync(0xffffffffu,s[r],off);
  }
  if(q<12){
    int j=q/3,d=q-3*j,e=g2*4+j;
    atomicAdd(&g_xacc[rwb[e]*3+d], dfb[e*3+d]*s[j]*icb[e]);
  }
}

// node: x+=xacc; t=silu([h|agg]@NW1+nb1); h+=t@NW2+nb2; next-layer A/B or final out (validated)
__global__ void __launch_bounds__(256) k_node(
    const float* __restrict__ NW1,const float* __restrict__ nb1,
    const float* __restrict__ NW2,const float* __restrict__ nb2,
    const float* __restrict__ WA,const float* __restrict__ ba,
    const float* __restrict__ WB,int last,float* __restrict__ outp){
  extern __shared__ char sr[];
  u64* sN1p=(u64*)sr;
  u64* sN2p=(u64*)(sr+32768);
  u64* sAp =(u64*)(sr+49152);
  float* snb1=(float*)(sr+65536); float* snb2=(float*)(sr+65792);
  float* sba=(float*)(sr+66048);
  float* vbase=(float*)(sr+66304);
  const int tid=threadIdx.x,wid=tid>>5,lane=tid&31,q=lane&15,g2=lane>>4;
  stageW(sN1p,NW1,128,tid,256);
  stageW(sN2p,NW2,64,tid,256);
  stageW(sAp,WA,64,tid,256);
  if(tid<64){snb1[tid]=nb1[tid];snb2[tid]=nb2[tid];sba[tid]=ba[tid];}
  float* vb=vbase+wid*1056;
  int nbase=blockIdx.x*64+wid*8;
#pragma unroll
  for(int t=0;t<4;t++){
    int e=t*2+g2,n=nbase+e;
    float4 h4=make_float4(0,0,0,0),a4=make_float4(0,0,0,0);
    if(n<NN){
      h4=*(const float4*)&g_h[n*64+q*4];
      a4=*(const float4*)&g_agg[n*64+q*4];
      *(float4*)&g_agg[n*64+q*4]=make_float4(0,0,0,0);
    }
    *(float4*)&vb[e*132+q*4]=h4;
    *(float4*)&vb[e*132+64+q*4]=a4;
  }
  if(lane<24){
    int e=lane/3,d=lane-3*(lane/3),n=nbase+e;
    if(n<NN){
      float nx=g_x[n*3+d]+g_xacc[n*3+d];
      g_x[n*3+d]=nx; g_xacc[n*3+d]=0.f;
      if(last) outp[NN*64+n*3+d]=nx;
    }
  }
  __syncthreads();
  u64 acc[16];
  ainit(acc,snb1,q);
  mv8p<128>(vb+g2*4*132,132,sN1p,q,acc);
  __syncwarp();
#pragma unroll
  for(int r=0;r<4;r++){
    int e=g2*4+r;
    *(float4*)&vb[e*132+64+q*4]=make_float4(
      silu(fin(acc[4*r])),silu(fin(acc[4*r+1])),silu(fin(acc[4*r+2])),silu(fin(acc[4*r+3])));
  }
  __syncthreads();
  if(!last) stageW(sN1p,WB,64,tid,256);
  ainit(acc,snb2,q);
  mv8p<64>(vb+g2*4*132+64,132,sN2p,q,acc);
  __syncwarp();
#pragma unroll
  for(int r=0;r<4;r++){
    int e=g2*4+r,n=nbase+e;
    float4 ho=*(const float4*)&vb[e*132+q*4];
    float4 hn=make_float4(ho.x+fin(acc[4*r]),ho.y+fin(acc[4*r+1]),
                          ho.z+fin(acc[4*r+2]),ho.w+fin(acc[4*r+3]));
    *(float4*)&vb[e*132+q*4]=hn;
    if(n<NN) *(float4*)&g_h[n*64+q*4]=hn;
  }
  __syncthreads();
  ainit(acc,sba,q);
  mv8p<64>(vb+g2*4*132,132,sAp,q,acc);
  if(last){
#pragma unroll
    for(int r=0;r<4;r++){
      int n=nbase+g2*4+r;
      if(n<NN) *(float4*)&outp[n*64+q*4]=make_float4(fin(acc[4*r]),fin(acc[4*r+1]),fin(acc[4*r+2]),fin(acc[4*r+3]));
    }
  } else {
#pragma unroll
    for(int r=0;r<4;r++){
      int n=nbase+g2*4+r;
      if(n<NN) *(float4*)&g_A[n*64+q*4]=make_float4(fin(acc[4*r]),fin(acc[4*r+1]),fin(acc[4*r+2]),fin(acc[4*r+3]));
    }
    a0init(acc);
    mv8p<64>(vb+g2*4*132,132,sN1p,q,acc);
#pragma unroll
    for(int r=0;r<4;r++){
      int n=nbase+g2*4+r;
      if(n<NN) *(float4*)&g_B[n*64+q*4]=make_float4(fin(acc[4*r]),fin(acc[4*r+1]),fin(acc[4*r+2]),fin(acc[4*r+3]));
    }
  }
}

extern "C" void kernel_launch(void* const* d_in,const int* in_sizes,int n_in,
                              void* d_out,int out_size){
  const float* h16=(const float*)d_in[0];
  const float* xin=(const float*)d_in[1];
  const int*   ei =(const int*  )d_in[2];
  const float* Wi =(const float*)d_in[3];
  const float* bi =(const float*)d_in[4];
  const float* ew1=(const float*)d_in[5];
  const float* eb1=(const float*)d_in[6];
  const float* ew2=(const float*)d_in[7];
  const float* eb2=(const float*)d_in[8];
  const float* cw1=(const float*)d_in[9];
  const float* cb1=(const float*)d_in[10];
  const float* cw2=(const float*)d_in[11];
  const float* nw1=(const float*)d_in[12];
  const float* nb1=(const float*)d_in[13];
  const float* nw2=(const float*)d_in[14];
  const float* nb2=(const float*)d_in[15];
  const float* Wo =(const float*)d_in[16];
  const float* bo =(const float*)d_in[17];
  float* outp=(float*)d_out;
  const int* erow=ei; const int* ecol=ei+EE;

  const int SME=58880, SMEDGE=(8448+8*1152)*4, SMN=100096;
  cudaFuncSetAttribute(k_embed,cudaFuncAttributeMaxDynamicSharedMemorySize,SME);
  cudaFuncSetAttribute(k_edge, cudaFuncAttributeMaxDynamicSharedMemorySize,SMEDGE);
  cudaFuncSetAttribute(k_node, cudaFuncAttributeMaxDynamicSharedMemorySize,SMN);

  const int NB=(NN+63)/64;
  k_zero<<<(NN*3+255)/256,256>>>();
  k_count<<<(EE+255)/256,256>>>(erow);
  k_embed<<<NB,256,SME>>>(h16,xin,Wi,bi,ew1,eb1,ew1+64*64);
  for(int l=0;l<4;l++){
    k_edge<<<EE/64,256,SMEDGE>>>(erow,ecol,ew1+l*129*64+128*64,ew2+l*4096,eb2+l*64,
                                 cw1+l*4096,cb1+l*64,cw2+l*64);
    int last=(l==3);
    const float* WA = last ? Wo : ew1+(l+1)*129*64;
    const float* ba = last ? bo : eb1+(l+1)*64;
    const float* WB = last ? Wo : WA+64*64;
    k_node<<<NB,256,SMN>>>(nw1+l*128*64,nb1+l*64,nw2+l*4096,nb2+l*64,WA,ba,WB,last,outp);
  }
}

// round 12
// speedup vs baseline: 1.3837x; 1.0386x over previous
#include <cuda_runtime.h>
#include <cstdint>
#define NN 20000
#define EE 320000
using u64 = unsigned long long;

__device__ float g_x[NN*3];
__device__ float g_h[NN*64];
__device__ float g_A[NN*64];
__device__ float g_B[NN*64];
__device__ float g_agg[NN*64];
__device__ float g_xacc[NN*3];
__device__ float g_cnt[NN];
__device__ float g_invc[NN];

__device__ __forceinline__ float silu(float v){ return __fdividef(v,1.f+__expf(-v)); }
__device__ __forceinline__ u64 mk2(float a,float b){u64 r;asm("mov.b64 %0,{%1,%2};":"=l"(r):"f"(a),"f"(b));return r;}
__device__ __forceinline__ u64 pack2(float x){u64 r;asm("mov.b64 %0,{%1,%1};":"=l"(r):"f"(x));return r;}
__device__ __forceinline__ u64 ffma2(u64 a,u64 b,u64 c){u64 d;asm("fma.rn.f32x2 %0,%1,%2,%3;":"=l"(d):"l"(a),"l"(b),"l"(c));return d;}
__device__ __forceinline__ float2 unpk(u64 a){float x,y;asm("mov.b64 {%0,%1},%2;":"=f"(x),"=f"(y):"l"(a));return make_float2(x,y);}
__device__ __forceinline__ float fin(u64 a){float2 v=unpk(a);return v.x+v.y;}

// ======== dual-width edge matvec: 16 rows x W[K,64], row-major weights ========
// q=lane&15 -> out cols [4q,4q+4). Half-warp g2 owns rows e=2r+g2, r=0..7,
// staged at vb=base+g2*68 with row stride 136. accA: r=0..3, accB: r=4..7;
// acc[2r']=cols(4q,4q+1), acc[2r'+1]=cols(4q+2,4q+3).
template<int K>
__device__ __forceinline__ void mv8d(const float* vb,const float* W,int q,u64* accA,u64* accB){
#pragma unroll 2
  for(int k4=0;k4<K;k4+=4){
    float va[8][4];
#pragma unroll
    for(int r=0;r<8;r++){
      float4 a=*(const float4*)(vb+r*136+k4);
      va[r][0]=a.x; va[r][1]=a.y; va[r][2]=a.z; va[r][3]=a.w;
    }
#pragma unroll
    for(int j=0;j<4;j++){
      ulonglong2 w=*(const ulonglong2*)(W+(k4+j)*64+q*4);
#pragma unroll
      for(int r=0;r<4;r++){
        u64 p=pack2(va[r][j]);
        accA[2*r]  =ffma2(w.x,p,accA[2*r]);
        accA[2*r+1]=ffma2(w.y,p,accA[2*r+1]);
      }
#pragma unroll
      for(int r=0;r<4;r++){
        u64 p=pack2(va[r+4][j]);
        accB[2*r]  =ffma2(w.x,p,accB[2*r]);
        accB[2*r+1]=ffma2(w.y,p,accB[2*r+1]);
      }
    }
  }
}
__device__ __forceinline__ void acc_init8(u64* acc,const float* sb,int q){
  u64 b01=((const u64*)sb)[q*2], b23=((const u64*)sb)[q*2+1];
#pragma unroll
  for(int r=0;r<4;r++){ acc[2*r]=b01; acc[2*r+1]=b23; }
}

// ======== node-side scalar machinery (validated R4/R7/R9/R11) ========
__device__ __forceinline__ void stageW(u64* dst,const float* __restrict__ src,int K,int tid,int nthr){
  int tot=(K/2)*64;
  for(int i=tid;i<tot;i+=nthr){
    int kp=i>>6,c=i&63;
    u64 v=mk2(src[(2*kp)*64+c],src[(2*kp+1)*64+c]);
    dst[(kp<<6)+((c&2)?32:0)+((c>>2)<<1)+(c&1)]=v;
  }
}
__device__ __forceinline__ void ainit(u64* acc,const float* b4,int q){
  float4 b=*(const float4*)&b4[q*4];
#pragma unroll
  for(int r=0;r<4;r++){
    acc[4*r]=mk2(b.x,0.f); acc[4*r+1]=mk2(b.y,0.f);
    acc[4*r+2]=mk2(b.z,0.f); acc[4*r+3]=mk2(b.w,0.f);
  }
}
__device__ __forceinline__ void a0init(u64* acc){
#pragma unroll
  for(int i=0;i<16;i++) acc[i]=0ull;
}
template<int K>
__device__ __forceinline__ void mv8p(const float* vb,int ST,const u64* Wp,int q,u64* acc){
#pragma unroll 8
  for(int kp=0;kp<K/2;kp+=2){
    ulonglong2 a0=*(const ulonglong2*)(vb+2*kp);
    ulonglong2 a1=*(const ulonglong2*)(vb+ST+2*kp);
    ulonglong2 a2=*(const ulonglong2*)(vb+2*ST+2*kp);
    ulonglong2 a3=*(const ulonglong2*)(vb+3*ST+2*kp);
    const u64* wr=Wp+(kp<<6)+2*q;
    ulonglong2 wa0=*(const ulonglong2*)wr;
    ulonglong2 wb0=*(const ulonglong2*)(wr+32);
    ulonglong2 wa1=*(const ulonglong2*)(wr+64);
    ulonglong2 wb1=*(const ulonglong2*)(wr+96);
#define RSTEP(r,A) \
    acc[4*r+0]=ffma2(A.x,wa0.x,acc[4*r+0]); acc[4*r+1]=ffma2(A.x,wa0.y,acc[4*r+1]); \
    acc[4*r+2]=ffma2(A.x,wb0.x,acc[4*r+2]); acc[4*r+3]=ffma2(A.x,wb0.y,acc[4*r+3]); \
    acc[4*r+0]=ffma2(A.y,wa1.x,acc[4*r+0]); acc[4*r+1]=ffma2(A.y,wa1.y,acc[4*r+1]); \
    acc[4*r+2]=ffma2(A.y,wb1.x,acc[4*r+2]); acc[4*r+3]=ffma2(A.y,wb1.y,acc[4*r+3]);
    RSTEP(0,a0) RSTEP(1,a1) RSTEP(2,a2) RSTEP(3,a3)
#undef RSTEP
  }
}

__global__ void k_zero(){
  int i=blockIdx.x*blockDim.x+threadIdx.x;
  if(i<NN) g_cnt[i]=0.f;
  if(i<NN*3) g_xacc[i]=0.f;
}
__global__ void k_count(const int* __restrict__ erow){
  int e=blockIdx.x*blockDim.x+threadIdx.x;
  if(e<EE) atomicAdd(&g_cnt[erow[e]],1.f);
}

// h0=h16@Wi+bi ; A=h0@EA+eb ; B=h0@EB ; init x, invc, agg=0  (validated)
__global__ void __launch_bounds__(256) k_embed(
    const float* __restrict__ h16,const float* __restrict__ xin,
    const float* __restrict__ Wi,const float* __restrict__ bi,
    const float* __restrict__ EA,const float* __restrict__ eb,
    const float* __restrict__ EB){
  extern __shared__ char sr[];
  u64* sWip=(u64*)sr; u64* sEAp=(u64*)(sr+4096); u64* sEBp=(u64*)(sr+20480);
  float* sbi=(float*)(sr+36864); float* seb=(float*)(sr+37120);
  float* vbase=(float*)(sr+37376);
  const int tid=threadIdx.x,wid=tid>>5,lane=tid&31,q=lane&15,g2=lane>>4;
  stageW(sWip,Wi,16,tid,256);
  stageW(sEAp,EA,64,tid,256);
  stageW(sEBp,EB,64,tid,256);
  if(tid<64){sbi[tid]=bi[tid];seb[tid]=eb[tid];}
  float* vb=vbase+wid*(8*84);
  int nbase=blockIdx.x*64+wid*8;
#pragma unroll
  for(int t=0;t<4;t++){
    int e=t*2+g2,n=nbase+e;
    if(q<4){
      float4 v=make_float4(0,0,0,0);
      if(n<NN) v=*(const float4*)&h16[n*16+q*4];
      *(float4*)&vb[e*84+q*4]=v;
    }
    if(n<NN) *(float4*)&g_agg[n*64+q*4]=make_float4(0,0,0,0);
  }
  if(lane<8){int n=nbase+lane; if(n<NN) g_invc[n]=__fdividef(1.f,fmaxf(g_cnt[n],1.f));}
  if(lane<24){int e=lane/3,d=lane-3*(lane/3),n=nbase+e; if(n<NN) g_x[n*3+d]=xin[n*3+d];}
  __syncthreads();
  u64 acc[16];
  ainit(acc,sbi,q);
  mv8p<16>(vb+g2*4*84,84,sWip,q,acc);
  __syncwarp();
#pragma unroll
  for(int r=0;r<4;r++){
    int e=g2*4+r,n=nbase+e;
    float4 h0=make_float4(fin(acc[4*r]),fin(acc[4*r+1]),fin(acc[4*r+2]),fin(acc[4*r+3]));
    *(float4*)&vb[e*84+16+q*4]=h0;
    if(n<NN) *(float4*)&g_h[n*64+q*4]=h0;
  }
  __syncwarp();
  ainit(acc,seb,q);
  mv8p<64>(vb+g2*4*84+16,84,sEAp,q,acc);
#pragma unroll
  for(int r=0;r<4;r++){
    int n=nbase+g2*4+r;
    if(n<NN) *(float4*)&g_A[n*64+q*4]=make_float4(fin(acc[4*r]),fin(acc[4*r+1]),fin(acc[4*r+2]),fin(acc[4*r+3]));
  }
  a0init(acc);
  mv8p<64>(vb+g2*4*84+16,84,sEBp,q,acc);
#pragma unroll
  for(int r=0;r<4;r++){
    int n=nbase+g2*4+r;
    if(n<NN) *(float4*)&g_B[n*64+q*4]=make_float4(fin(acc[4*r]),fin(acc[4*r+1]),fin(acc[4*r+2]),fin(acc[4*r+3]));
  }
}

// ======== edge kernel: 16 edges/warp, 128 edges/block (dual-width R3) ========
// smem: sW2 0(16K), sC1 16384(16K), w1c/b2/cb1/cw2 32768..33792,
// per-warp wsm = 33792 + wid*9216: m1b 0 (1088f), mb 1088 (1088f),
// dfb 2176 (48f), rdb 2224 (16f), icb 2240 (16f), rwb 2256, clb 2272 -> 2304f.
__global__ void __launch_bounds__(256,2) k_edge(
    const int* __restrict__ erow,const int* __restrict__ ecol,
    const float* __restrict__ w1c,const float* __restrict__ W2,
    const float* __restrict__ b2,const float* __restrict__ CW1,
    const float* __restrict__ cb1,const float* __restrict__ cw2){
  extern __shared__ char sr[];
  float* sW2=(float*)sr; float* sC1=(float*)(sr+16384);
  float* sw1c=(float*)(sr+32768); float* sb2=(float*)(sr+33024);
  float* scb1=(float*)(sr+33280); float* scw2=(float*)(sr+33536);
  float* wsmb=(float*)(sr+33792);
  const int tid=threadIdx.x,wid=tid>>5,lane=tid&31,q=lane&15,g2=lane>>4;
  for(int i=tid;i<1024;i+=256){((float4*)sW2)[i]=((const float4*)W2)[i];((float4*)sC1)[i]=((const float4*)CW1)[i];}
  if(tid<64){sw1c[tid]=w1c[tid];sb2[tid]=b2[tid];scb1[tid]=cb1[tid];scw2[tid]=cw2[tid];}
  float* wsm=wsmb+wid*2304;
  float* m1b=wsm; float* mb=wsm+1088; float* dfb=wsm+2176;
  float* rdb=wsm+2224; float* icb=wsm+2240;
  int* rwb=(int*)(wsm+2256); int* clb=(int*)(wsm+2272);
  int ebase=blockIdx.x*128+wid*16;
  if(lane<16){
    int e=ebase+lane,r=erow[e],c=ecol[e];
    rwb[lane]=r; clb[lane]=c;
    float dx=g_x[r*3]-g_x[c*3],dy=g_x[r*3+1]-g_x[c*3+1],dz=g_x[r*3+2]-g_x[c*3+2];
    dfb[lane*3]=dx; dfb[lane*3+1]=dy; dfb[lane*3+2]=dz;
    rdb[lane]=dx*dx+dy*dy+dz*dz; icb[lane]=g_invc[r];
  }
  __syncthreads();
  { // m1 = silu(A[r]+B[c]+rad*w1c), 16 edges
    float4 wc=*(const float4*)&sw1c[q*4];
#pragma unroll
    for(int t=0;t<8;t++){
      int e=t*2+g2;
      float4 av=*(const float4*)&g_A[rwb[e]*64+q*4];
      float4 bv=*(const float4*)&g_B[clb[e]*64+q*4];
      float rad=rdb[e];
      *(float4*)&m1b[e*68+q*4]=make_float4(
        silu(av.x+bv.x+rad*wc.x), silu(av.y+bv.y+rad*wc.y),
        silu(av.z+bv.z+rad*wc.z), silu(av.w+bv.w+rad*wc.w));
    }
  }
  __syncwarp();
  u64 accA[8],accB[8];
  acc_init8(accA,sb2,q); acc_init8(accB,sb2,q);
  mv8d<64>(m1b+g2*68,sW2,q,accA,accB);
#pragma unroll
  for(int r=0;r<8;r++){
    int e=2*r+g2;
    const u64* ac=(r<4)?(accA+2*(r&3)):(accB+2*(r&3));
    float2 lo=unpk(ac[0]),hi=unpk(ac[1]);
    float m0=silu(lo.x),m1=silu(lo.y),m2=silu(hi.x),m3=silu(hi.y);
    *(float4*)&mb[e*68+q*4]=make_float4(m0,m1,m2,m3);
    float* ap=&g_agg[rwb[e]*64+q*4];
    asm volatile("red.global.add.v4.f32 [%0],{%1,%2,%3,%4};"
                 ::"l"(ap),"f"(m0),"f"(m1),"f"(m2),"f"(m3):"memory");
  }
  __syncwarp();
  acc_init8(accA,scb1,q); acc_init8(accB,scb1,q);
  mv8d<64>(mb+g2*68,sC1,q,accA,accB);
  float4 c4=*(const float4*)&scw2[q*4];
  float s[8];
#pragma unroll
  for(int r=0;r<8;r++){
    const u64* ac=(r<4)?(accA+2*(r&3)):(accB+2*(r&3));
    float2 lo=unpk(ac[0]),hi=unpk(ac[1]);
    s[r]=silu(lo.x)*c4.x+silu(lo.y)*c4.y+silu(hi.x)*c4.z+silu(hi.y)*c4.w;
  }
#pragma unroll
  for(int off=1;off<16;off<<=1){
#pragma unroll
    for(int r=0;r<8;r++) s[r]+=__shfl_xor_sync(0xffffffffu,s[r],off);
  }
  if(q<12){
    int j=q/3,d=q-3*j;
    int e0=2*j+g2, e1=2*(j+4)+g2;
    atomicAdd(&g_xacc[rwb[e0]*3+d], dfb[e0*3+d]*s[j]*icb[e0]);
    atomicAdd(&g_xacc[rwb[e1]*3+d], dfb[e1*3+d]*s[j+4]*icb[e1]);
  }
}

// node: x+=xacc; t=silu([h|agg]@NW1+nb1); h+=t@NW2+nb2; next-layer A/B or final out (validated)
__global__ void __launch_bounds__(256) k_node(
    const float* __restrict__ NW1,const float* __restrict__ nb1,
    const float* __restrict__ NW2,const float* __restrict__ nb2,
    const float* __restrict__ WA,const float* __restrict__ ba,
    const float* __restrict__ WB,int last,float* __restrict__ outp){
  extern __shared__ char sr[];
  u64* sN1p=(u64*)sr;
  u64* sN2p=(u64*)(sr+32768);
  u64* sAp =(u64*)(sr+49152);
  float* snb1=(float*)(sr+65536); float* snb2=(float*)(sr+65792);
  float* sba=(float*)(sr+66048);
  float* vbase=(float*)(sr+66304);
  const int tid=threadIdx.x,wid=tid>>5,lane=tid&31,q=lane&15,g2=lane>>4;
  stageW(sN1p,NW1,128,tid,256);
  stageW(sN2p,NW2,64,tid,256);
  stageW(sAp,WA,64,tid,256);
  if(tid<64){snb1[tid]=nb1[tid];snb2[tid]=nb2[tid];sba[tid]=ba[tid];}
  float* vb=vbase+wid*1056;
  int nbase=blockIdx.x*64+wid*8;
#pragma unroll
  for(int t=0;t<4;t++){
    int e=t*2+g2,n=nbase+e;
    float4 h4=make_float4(0,0,0,0),a4=make_float4(0,0,0,0);
    if(n<NN){
      h4=*(const float4*)&g_h[n*64+q*4];
      a4=*(const float4*)&g_agg[n*64+q*4];
      *(float4*)&g_agg[n*64+q*4]=make_float4(0,0,0,0);
    }
    *(float4*)&vb[e*132+q*4]=h4;
    *(float4*)&vb[e*132+64+q*4]=a4;
  }
  if(lane<24){
    int e=lane/3,d=lane-3*(lane/3),n=nbase+e;
    if(n<NN){
      float nx=g_x[n*3+d]+g_xacc[n*3+d];
      g_x[n*3+d]=nx; g_xacc[n*3+d]=0.f;
      if(last) outp[NN*64+n*3+d]=nx;
    }
  }
  __syncthreads();
  u64 acc[16];
  ainit(acc,snb1,q);
  mv8p<128>(vb+g2*4*132,132,sN1p,q,acc);
  __syncwarp();
#pragma unroll
  for(int r=0;r<4;r++){
    int e=g2*4+r;
    *(float4*)&vb[e*132+64+q*4]=make_float4(
      silu(fin(acc[4*r])),silu(fin(acc[4*r+1])),silu(fin(acc[4*r+2])),silu(fin(acc[4*r+3])));
  }
  __syncthreads();
  if(!last) stageW(sN1p,WB,64,tid,256);
  ainit(acc,snb2,q);
  mv8p<64>(vb+g2*4*132+64,132,sN2p,q,acc);
  __syncwarp();
#pragma unroll
  for(int r=0;r<4;r++){
    int e=g2*4+r,n=nbase+e;
    float4 ho=*(const float4*)&vb[e*132+q*4];
    float4 hn=make_float4(ho.x+fin(acc[4*r]),ho.y+fin(acc[4*r+1]),
                          ho.z+fin(acc[4*r+2]),ho.w+fin(acc[4*r+3]));
    *(float4*)&vb[e*132+q*4]=hn;
    if(n<NN) *(float4*)&g_h[n*64+q*4]=hn;
  }
  __syncthreads();
  ainit(acc,sba,q);
  mv8p<64>(vb+g2*4*132,132,sAp,q,acc);
  if(last){
#pragma unroll
    for(int r=0;r<4;r++){
      int n=nbase+g2*4+r;
      if(n<NN) *(float4*)&outp[n*64+q*4]=make_float4(fin(acc[4*r]),fin(acc[4*r+1]),fin(acc[4*r+2]),fin(acc[4*r+3]));
    }
  } else {
#pragma unroll
    for(int r=0;r<4;r++){
      int n=nbase+g2*4+r;
      if(n<NN) *(float4*)&g_A[n*64+q*4]=make_float4(fin(acc[4*r]),fin(acc[4*r+1]),fin(acc[4*r+2]),fin(acc[4*r+3]));
    }
    a0init(acc);
    mv8p<64>(vb+g2*4*132,132,sN1p,q,acc);
#pragma unroll
    for(int r=0;r<4;r++){
      int n=nbase+g2*4+r;
      if(n<NN) *(float4*)&g_B[n*64+q*4]=make_float4(fin(acc[4*r]),fin(acc[4*r+1]),fin(acc[4*r+2]),fin(acc[4*r+3]));
    }
  }
}

extern "C" void kernel_launch(void* const* d_in,const int* in_sizes,int n_in,
                              void* d_out,int out_size){
  const float* h16=(const float*)d_in[0];
  const float* xin=(const float*)d_in[1];
  const int*   ei =(const int*  )d_in[2];
  const float* Wi =(const float*)d_in[3];
  const float* bi =(const float*)d_in[4];
  const float* ew1=(const float*)d_in[5];
  const float* eb1=(const float*)d_in[6];
  const float* ew2=(const float*)d_in[7];
  const float* eb2=(const float*)d_in[8];
  const float* cw1=(const float*)d_in[9];
  const float* cb1=(const float*)d_in[10];
  const float* cw2=(const float*)d_in[11];
  const float* nw1=(const float*)d_in[12];
  const float* nb1=(const float*)d_in[13];
  const float* nw2=(const float*)d_in[14];
  const float* nb2=(const float*)d_in[15];
  const float* Wo =(const float*)d_in[16];
  const float* bo =(const float*)d_in[17];
  float* outp=(float*)d_out;
  const int* erow=ei; const int* ecol=ei+EE;

  const int SME=58880, SMEDGE=(8448+8*2304)*4, SMN=100096;
  cudaFuncSetAttribute(k_embed,cudaFuncAttributeMaxDynamicSharedMemorySize,SME);
  cudaFuncSetAttribute(k_edge, cudaFuncAttributeMaxDynamicSharedMemorySize,SMEDGE);
  cudaFuncSetAttribute(k_node, cudaFuncAttributeMaxDynamicSharedMemorySize,SMN);

  const int NB=(NN+63)/64;
  k_zero<<<(NN*3+255)/256,256>>>();
  k_count<<<(EE+255)/256,256>>>(erow);
  k_embed<<<NB,256,SME>>>(h16,xin,Wi,bi,ew1,eb1,ew1+64*64);
  for(int l=0;l<4;l++){
    k_edge<<<EE/128,256,SMEDGE>>>(erow,ecol,ew1+l*129*64+128*64,ew2+l*4096,eb2+l*64,
                                  cw1+l*4096,cb1+l*64,cw2+l*64);
    int last=(l==3);
    const float* WA = last ? Wo : ew1+(l+1)*129*64;
    const float* ba = last ? bo : eb1+(l+1)*64;
    const float* WB = last ? Wo : WA+64*64;
    k_node<<<NB,256,SMN>>>(nw1+l*128*64,nb1+l*64,nw2+l*4096,nb2+l*64,WA,ba,WB,last,outp);
  }
}

// round 13
// speedup vs baseline: 1.4273x; 1.0315x over previous
#include <cuda_runtime.h>
#include <cstdint>
#define NN 20000
#define EE 320000
using u64 = unsigned long long;

__device__ float g_x[NN*3];
__device__ float g_h[NN*64];
__device__ float g_A[NN*64];
__device__ float g_B[NN*64];
__device__ float g_agg[NN*64];
__device__ float g_xacc[NN*3];
__device__ float g_cnt[NN];
__device__ float g_invc[NN];

__device__ __forceinline__ float silu(float v){ return __fdividef(v,1.f+__expf(-v)); }
__device__ __forceinline__ u64 mk2(float a,float b){u64 r;asm("mov.b64 %0,{%1,%2};":"=l"(r):"f"(a),"f"(b));return r;}
__device__ __forceinline__ u64 pack2(float x){u64 r;asm("mov.b64 %0,{%1,%1};":"=l"(r):"f"(x));return r;}
__device__ __forceinline__ u64 ffma2(u64 a,u64 b,u64 c){u64 d;asm("fma.rn.f32x2 %0,%1,%2,%3;":"=l"(d):"l"(a),"l"(b),"l"(c));return d;}
__device__ __forceinline__ float2 unpk(u64 a){float x,y;asm("mov.b64 {%0,%1},%2;":"=f"(x),"=f"(y):"l"(a));return make_float2(x,y);}
__device__ __forceinline__ float fin(u64 a){float2 v=unpk(a);return v.x+v.y;}

// ======== dual-width edge matvec, register-lean row-chunked version ========
// q=lane&15 -> out cols [4q,4q+4). Half-warp g2 owns rows e=2r+g2, r=0..7,
// staged at vb=base+g2*68 with row stride 136. accA: rows 0-3, accB: rows 4-7.
template<int K>
__device__ __forceinline__ void mv8d(const float* vb,const float* W,int q,u64* accA,u64* accB){
#pragma unroll 2
  for(int k4=0;k4<K;k4+=4){
    ulonglong2 w0=*(const ulonglong2*)(W+(k4+0)*64+q*4);
    ulonglong2 w1=*(const ulonglong2*)(W+(k4+1)*64+q*4);
    ulonglong2 w2=*(const ulonglong2*)(W+(k4+2)*64+q*4);
    ulonglong2 w3=*(const ulonglong2*)(W+(k4+3)*64+q*4);
#pragma unroll
    for(int h=0;h<2;h++){
      u64* acc = h? accB : accA;
      const float* vp=vb+(h*4)*136+k4;
      float4 a0=*(const float4*)(vp);
      float4 a1=*(const float4*)(vp+136);
      float4 a2=*(const float4*)(vp+272);
      float4 a3=*(const float4*)(vp+408);
#define RJ(w,f0,f1,f2,f3) { \
      u64 p0=pack2(f0),p1=pack2(f1),p2=pack2(f2),p3=pack2(f3); \
      acc[0]=ffma2(w.x,p0,acc[0]); acc[1]=ffma2(w.y,p0,acc[1]); \
      acc[2]=ffma2(w.x,p1,acc[2]); acc[3]=ffma2(w.y,p1,acc[3]); \
      acc[4]=ffma2(w.x,p2,acc[4]); acc[5]=ffma2(w.y,p2,acc[5]); \
      acc[6]=ffma2(w.x,p3,acc[6]); acc[7]=ffma2(w.y,p3,acc[7]); }
      RJ(w0,a0.x,a1.x,a2.x,a3.x)
      RJ(w1,a0.y,a1.y,a2.y,a3.y)
      RJ(w2,a0.z,a1.z,a2.z,a3.z)
      RJ(w3,a0.w,a1.w,a2.w,a3.w)
#undef RJ
    }
  }
}
__device__ __forceinline__ void acc_init8(u64* acc,const float* sb,int q){
  u64 b01=((const u64*)sb)[q*2], b23=((const u64*)sb)[q*2+1];
#pragma unroll
  for(int r=0;r<4;r++){ acc[2*r]=b01; acc[2*r+1]=b23; }
}

// ======== node-side scalar machinery (validated) ========
__device__ __forceinline__ void stageW(u64* dst,const float* __restrict__ src,int K,int tid,int nthr){
  int tot=(K/2)*64;
  for(int i=tid;i<tot;i+=nthr){
    int kp=i>>6,c=i&63;
    u64 v=mk2(src[(2*kp)*64+c],src[(2*kp+1)*64+c]);
    dst[(kp<<6)+((c&2)?32:0)+((c>>2)<<1)+(c&1)]=v;
  }
}
__device__ __forceinline__ void ainit(u64* acc,const float* b4,int q){
  float4 b=*(const float4*)&b4[q*4];
#pragma unroll
  for(int r=0;r<4;r++){
    acc[4*r]=mk2(b.x,0.f); acc[4*r+1]=mk2(b.y,0.f);
    acc[4*r+2]=mk2(b.z,0.f); acc[4*r+3]=mk2(b.w,0.f);
  }
}
__device__ __forceinline__ void a0init(u64* acc){
#pragma unroll
  for(int i=0;i<16;i++) acc[i]=0ull;
}
template<int K>
__device__ __forceinline__ void mv8p(const float* vb,int ST,const u64* Wp,int q,u64* acc){
#pragma unroll 8
  for(int kp=0;kp<K/2;kp+=2){
    ulonglong2 a0=*(const ulonglong2*)(vb+2*kp);
    ulonglong2 a1=*(const ulonglong2*)(vb+ST+2*kp);
    ulonglong2 a2=*(const ulonglong2*)(vb+2*ST+2*kp);
    ulonglong2 a3=*(const ulonglong2*)(vb+3*ST+2*kp);
    const u64* wr=Wp+(kp<<6)+2*q;
    ulonglong2 wa0=*(const ulonglong2*)wr;
    ulonglong2 wb0=*(const ulonglong2*)(wr+32);
    ulonglong2 wa1=*(const ulonglong2*)(wr+64);
    ulonglong2 wb1=*(const ulonglong2*)(wr+96);
#define RSTEP(r,A) \
    acc[4*r+0]=ffma2(A.x,wa0.x,acc[4*r+0]); acc[4*r+1]=ffma2(A.x,wa0.y,acc[4*r+1]); \
    acc[4*r+2]=ffma2(A.x,wb0.x,acc[4*r+2]); acc[4*r+3]=ffma2(A.x,wb0.y,acc[4*r+3]); \
    acc[4*r+0]=ffma2(A.y,wa1.x,acc[4*r+0]); acc[4*r+1]=ffma2(A.y,wa1.y,acc[4*r+1]); \
    acc[4*r+2]=ffma2(A.y,wb1.x,acc[4*r+2]); acc[4*r+3]=ffma2(A.y,wb1.y,acc[4*r+3]);
    RSTEP(0,a0) RSTEP(1,a1) RSTEP(2,a2) RSTEP(3,a3)
#undef RSTEP
  }
}

__global__ void k_zero(){
  int i=blockIdx.x*blockDim.x+threadIdx.x;
  if(i<NN) g_cnt[i]=0.f;
  if(i<NN*3) g_xacc[i]=0.f;
}
__global__ void k_count(const int* __restrict__ erow){
  int e=blockIdx.x*blockDim.x+threadIdx.x;
  if(e<EE) atomicAdd(&g_cnt[erow[e]],1.f);
}

// h0=h16@Wi+bi ; A=h0@EA+eb ; B=h0@EB ; init x, invc, agg=0  (validated)
__global__ void __launch_bounds__(256) k_embed(
    const float* __restrict__ h16,const float* __restrict__ xin,
    const float* __restrict__ Wi,const float* __restrict__ bi,
    const float* __restrict__ EA,const float* __restrict__ eb,
    const float* __restrict__ EB){
  extern __shared__ char sr[];
  u64* sWip=(u64*)sr; u64* sEAp=(u64*)(sr+4096); u64* sEBp=(u64*)(sr+20480);
  float* sbi=(float*)(sr+36864); float* seb=(float*)(sr+37120);
  float* vbase=(float*)(sr+37376);
  const int tid=threadIdx.x,wid=tid>>5,lane=tid&31,q=lane&15,g2=lane>>4;
  stageW(sWip,Wi,16,tid,256);
  stageW(sEAp,EA,64,tid,256);
  stageW(sEBp,EB,64,tid,256);
  if(tid<64){sbi[tid]=bi[tid];seb[tid]=eb[tid];}
  float* vb=vbase+wid*(8*84);
  int nbase=blockIdx.x*64+wid*8;
#pragma unroll
  for(int t=0;t<4;t++){
    int e=t*2+g2,n=nbase+e;
    if(q<4){
      float4 v=make_float4(0,0,0,0);
      if(n<NN) v=*(const float4*)&h16[n*16+q*4];
      *(float4*)&vb[e*84+q*4]=v;
    }
    if(n<NN) *(float4*)&g_agg[n*64+q*4]=make_float4(0,0,0,0);
  }
  if(lane<8){int n=nbase+lane; if(n<NN) g_invc[n]=__fdividef(1.f,fmaxf(g_cnt[n],1.f));}
  if(lane<24){int e=lane/3,d=lane-3*(lane/3),n=nbase+e; if(n<NN) g_x[n*3+d]=xin[n*3+d];}
  __syncthreads();
  u64 acc[16];
  ainit(acc,sbi,q);
  mv8p<16>(vb+g2*4*84,84,sWip,q,acc);
  __syncwarp();
#pragma unroll
  for(int r=0;r<4;r++){
    int e=g2*4+r,n=nbase+e;
    float4 h0=make_float4(fin(acc[4*r]),fin(acc[4*r+1]),fin(acc[4*r+2]),fin(acc[4*r+3]));
    *(float4*)&vb[e*84+16+q*4]=h0;
    if(n<NN) *(float4*)&g_h[n*64+q*4]=h0;
  }
  __syncwarp();
  ainit(acc,seb,q);
  mv8p<64>(vb+g2*4*84+16,84,sEAp,q,acc);
#pragma unroll
  for(int r=0;r<4;r++){
    int n=nbase+g2*4+r;
    if(n<NN) *(float4*)&g_A[n*64+q*4]=make_float4(fin(acc[4*r]),fin(acc[4*r+1]),fin(acc[4*r+2]),fin(acc[4*r+3]));
  }
  a0init(acc);
  mv8p<64>(vb+g2*4*84+16,84,sEBp,q,acc);
#pragma unroll
  for(int r=0;r<4;r++){
    int n=nbase+g2*4+r;
    if(n<NN) *(float4*)&g_B[n*64+q*4]=make_float4(fin(acc[4*r]),fin(acc[4*r+1]),fin(acc[4*r+2]),fin(acc[4*r+3]));
  }
}

// ======== edge kernel: 16 edges/warp, 128 edges/block, 3 CTAs/SM ========
// smem: sW2 0(16K), sC1 16384(16K), w1c/b2/cb1/cw2 32768..33792,
// per-warp wsm = 33792 + wid*4864: m1b 0 (1088f, reused as mb),
// dfb 1088, rdb 1136, icb 1152, rwb 1168, clb 1184 -> 1216f.
__global__ void __launch_bounds__(256,3) k_edge(
    const int* __restrict__ erow,const int* __restrict__ ecol,
    const float* __restrict__ w1c,const float* __restrict__ W2,
    const float* __restrict__ b2,const float* __restrict__ CW1,
    const float* __restrict__ cb1,const float* __restrict__ cw2){
  extern __shared__ char sr[];
  float* sW2=(float*)sr; float* sC1=(float*)(sr+16384);
  float* sw1c=(float*)(sr+32768); float* sb2=(float*)(sr+33024);
  float* scb1=(float*)(sr+33280); float* scw2=(float*)(sr+33536);
  float* wsmb=(float*)(sr+33792);
  const int tid=threadIdx.x,wid=tid>>5,lane=tid&31,q=lane&15,g2=lane>>4;
  for(int i=tid;i<1024;i+=256){((float4*)sW2)[i]=((const float4*)W2)[i];((float4*)sC1)[i]=((const float4*)CW1)[i];}
  if(tid<64){sw1c[tid]=w1c[tid];sb2[tid]=b2[tid];scb1[tid]=cb1[tid];scw2[tid]=cw2[tid];}
  float* wsm=wsmb+wid*1216;
  float* m1b=wsm;                 // 1088 floats, reused as mb after matvec1
  float* dfb=wsm+1088; float* rdb=wsm+1136; float* icb=wsm+1152;
  int* rwb=(int*)(wsm+1168); int* clb=(int*)(wsm+1184);
  int ebase=blockIdx.x*128+wid*16;
  if(lane<16){
    int e=ebase+lane,r=erow[e],c=ecol[e];
    rwb[lane]=r; clb[lane]=c;
    float dx=g_x[r*3]-g_x[c*3],dy=g_x[r*3+1]-g_x[c*3+1],dz=g_x[r*3+2]-g_x[c*3+2];
    dfb[lane*3]=dx; dfb[lane*3+1]=dy; dfb[lane*3+2]=dz;
    rdb[lane]=dx*dx+dy*dy+dz*dz; icb[lane]=g_invc[r];
  }
  __syncthreads();
  { // m1 = silu(A[r]+B[c]+rad*w1c), 16 edges
    float4 wc=*(const float4*)&sw1c[q*4];
#pragma unroll
    for(int t=0;t<8;t++){
      int e=t*2+g2;
      float4 av=*(const float4*)&g_A[rwb[e]*64+q*4];
      float4 bv=*(const float4*)&g_B[clb[e]*64+q*4];
      float rad=rdb[e];
      *(float4*)&m1b[e*68+q*4]=make_float4(
        silu(av.x+bv.x+rad*wc.x), silu(av.y+bv.y+rad*wc.y),
        silu(av.z+bv.z+rad*wc.z), silu(av.w+bv.w+rad*wc.w));
    }
  }
  __syncwarp();
  u64 accA[8],accB[8];
  acc_init8(accA,sb2,q); acc_init8(accB,sb2,q);
  mv8d<64>(m1b+g2*68,sW2,q,accA,accB);
  __syncwarp();          // all lanes done reading m1b before overwrite
#pragma unroll
  for(int r=0;r<8;r++){
    int e=2*r+g2;
    const u64* ac=(r<4)?(accA+2*(r&3)):(accB+2*(r&3));
    float2 lo=unpk(ac[0]),hi=unpk(ac[1]);
    float m0=silu(lo.x),m1=silu(lo.y),m2=silu(hi.x),m3=silu(hi.y);
    *(float4*)&m1b[e*68+q*4]=make_float4(m0,m1,m2,m3);
    float* ap=&g_agg[rwb[e]*64+q*4];
    asm volatile("red.global.add.v4.f32 [%0],{%1,%2,%3,%4};"
                 ::"l"(ap),"f"(m0),"f"(m1),"f"(m2),"f"(m3):"memory");
  }
  __syncwarp();
  acc_init8(accA,scb1,q); acc_init8(accB,scb1,q);
  mv8d<64>(m1b+g2*68,sC1,q,accA,accB);
  float4 c4=*(const float4*)&scw2[q*4];
  float s[8];
#pragma unroll
  for(int r=0;r<8;r++){
    const u64* ac=(r<4)?(accA+2*(r&3)):(accB+2*(r&3));
    float2 lo=unpk(ac[0]),hi=unpk(ac[1]);
    s[r]=silu(lo.x)*c4.x+silu(lo.y)*c4.y+silu(hi.x)*c4.z+silu(hi.y)*c4.w;
  }
#pragma unroll
  for(int off=1;off<16;off<<=1){
#pragma unroll
    for(int r=0;r<8;r++) s[r]+=__shfl_xor_sync(0xffffffffu,s[r],off);
  }
  if(q<12){
    int j=q/3,d=q-3*j;
    int e0=2*j+g2, e1=2*(j+4)+g2;
    atomicAdd(&g_xacc[rwb[e0]*3+d], dfb[e0*3+d]*s[j]*icb[e0]);
    atomicAdd(&g_xacc[rwb[e1]*3+d], dfb[e1*3+d]*s[j+4]*icb[e1]);
  }
}

// node: x+=xacc; t=silu([h|agg]@NW1+nb1); h+=t@NW2+nb2; next-layer A/B or final out (validated)
__global__ void __launch_bounds__(256) k_node(
    const float* __restrict__ NW1,const float* __restrict__ nb1,
    const float* __restrict__ NW2,const float* __restrict__ nb2,
    const float* __restrict__ WA,const float* __restrict__ ba,
    const float* __restrict__ WB,int last,float* __restrict__ outp){
  extern __shared__ char sr[];
  u64* sN1p=(u64*)sr;
  u64* sN2p=(u64*)(sr+32768);
  u64* sAp =(u64*)(sr+49152);
  float* snb1=(float*)(sr+65536); float* snb2=(float*)(sr+65792);
  float* sba=(float*)(sr+66048);
  float* vbase=(float*)(sr+66304);
  const int tid=threadIdx.x,wid=tid>>5,lane=tid&31,q=lane&15,g2=lane>>4;
  stageW(sN1p,NW1,128,tid,256);
  stageW(sN2p,NW2,64,tid,256);
  stageW(sAp,WA,64,tid,256);
  if(tid<64){snb1[tid]=nb1[tid];snb2[tid]=nb2[tid];sba[tid]=ba[tid];}
  float* vb=vbase+wid*1056;
  int nbase=blockIdx.x*64+wid*8;
#pragma unroll
  for(int t=0;t<4;t++){
    int e=t*2+g2,n=nbase+e;
    float4 h4=make_float4(0,0,0,0),a4=make_float4(0,0,0,0);
    if(n<NN){
      h4=*(const float4*)&g_h[n*64+q*4];
      a4=*(const float4*)&g_agg[n*64+q*4];
      *(float4*)&g_agg[n*64+q*4]=make_float4(0,0,0,0);
    }
    *(float4*)&vb[e*132+q*4]=h4;
    *(float4*)&vb[e*132+64+q*4]=a4;
  }
  if(lane<24){
    int e=lane/3,d=lane-3*(lane/3),n=nbase+e;
    if(n<NN){
      float nx=g_x[n*3+d]+g_xacc[n*3+d];
      g_x[n*3+d]=nx; g_xacc[n*3+d]=0.f;
      if(last) outp[NN*64+n*3+d]=nx;
    }
  }
  __syncthreads();
  u64 acc[16];
  ainit(acc,snb1,q);
  mv8p<128>(vb+g2*4*132,132,sN1p,q,acc);
  __syncwarp();
#pragma unroll
  for(int r=0;r<4;r++){
    int e=g2*4+r;
    *(float4*)&vb[e*132+64+q*4]=make_float4(
      silu(fin(acc[4*r])),silu(fin(acc[4*r+1])),silu(fin(acc[4*r+2])),silu(fin(acc[4*r+3])));
  }
  __syncthreads();
  if(!last) stageW(sN1p,WB,64,tid,256);
  ainit(acc,snb2,q);
  mv8p<64>(vb+g2*4*132+64,132,sN2p,q,acc);
  __syncwarp();
#pragma unroll
  for(int r=0;r<4;r++){
    int e=g2*4+r,n=nbase+e;
    float4 ho=*(const float4*)&vb[e*132+q*4];
    float4 hn=make_float4(ho.x+fin(acc[4*r]),ho.y+fin(acc[4*r+1]),
                          ho.z+fin(acc[4*r+2]),ho.w+fin(acc[4*r+3]));
    *(float4*)&vb[e*132+q*4]=hn;
    if(n<NN) *(float4*)&g_h[n*64+q*4]=hn;
  }
  __syncthreads();
  ainit(acc,sba,q);
  mv8p<64>(vb+g2*4*132,132,sAp,q,acc);
  if(last){
#pragma unroll
    for(int r=0;r<4;r++){
      int n=nbase+g2*4+r;
      if(n<NN) *(float4*)&outp[n*64+q*4]=make_float4(fin(acc[4*r]),fin(acc[4*r+1]),fin(acc[4*r+2]),fin(acc[4*r+3]));
    }
  } else {
#pragma unroll
    for(int r=0;r<4;r++){
      int n=nbase+g2*4+r;
      if(n<NN) *(float4*)&g_A[n*64+q*4]=make_float4(fin(acc[4*r]),fin(acc[4*r+1]),fin(acc[4*r+2]),fin(acc[4*r+3]));
    }
    a0init(acc);
    mv8p<64>(vb+g2*4*132,132,sN1p,q,acc);
#pragma unroll
    for(int r=0;r<4;r++){
      int n=nbase+g2*4+r;
      if(n<NN) *(float4*)&g_B[n*64+q*4]=make_float4(fin(acc[4*r]),fin(acc[4*r+1]),fin(acc[4*r+2]),fin(acc[4*r+3]));
    }
  }
}

extern "C" void kernel_launch(void* const* d_in,const int* in_sizes,int n_in,
                              void* d_out,int out_size){
  const float* h16=(const float*)d_in[0];
  const float* xin=(const float*)d_in[1];
  const int*   ei =(const int*  )d_in[2];
  const float* Wi =(const float*)d_in[3];
  const float* bi =(const float*)d_in[4];
  const float* ew1=(const float*)d_in[5];
  const float* eb1=(const float*)d_in[6];
  const float* ew2=(const float*)d_in[7];
  const float* eb2=(const float*)d_in[8];
  const float* cw1=(const float*)d_in[9];
  const float* cb1=(const float*)d_in[10];
  const float* cw2=(const float*)d_in[11];
  const float* nw1=(const float*)d_in[12];
  const float* nb1=(const float*)d_in[13];
  const float* nw2=(const float*)d_in[14];
  const float* nb2=(const float*)d_in[15];
  const float* Wo =(const float*)d_in[16];
  const float* bo =(const float*)d_in[17];
  float* outp=(float*)d_out;
  const int* erow=ei; const int* ecol=ei+EE;

  const int SME=58880, SMEDGE=(8448+8*1216)*4, SMN=100096;
  cudaFuncSetAttribute(k_embed,cudaFuncAttributeMaxDynamicSharedMemorySize,SME);
  cudaFuncSetAttribute(k_edge, cudaFuncAttributeMaxDynamicSharedMemorySize,SMEDGE);
  cudaFuncSetAttribute(k_node, cudaFuncAttributeMaxDynamicSharedMemorySize,SMN);

  const int NB=(NN+63)/64;
  k_zero<<<(NN*3+255)/256,256>>>();
  k_count<<<(EE+255)/256,256>>>(erow);
  k_embed<<<NB,256,SME>>>(h16,xin,Wi,bi,ew1,eb1,ew1+64*64);
  for(int l=0;l<4;l++){
    k_edge<<<EE/128,256,SMEDGE>>>(erow,ecol,ew1+l*129*64+128*64,ew2+l*4096,eb2+l*64,
                                  cw1+l*4096,cb1+l*64,cw2+l*64);
    int last=(l==3);
    const float* WA = last ? Wo : ew1+(l+1)*129*64;
    const float* ba = last ? bo : eb1+(l+1)*64;
    const float* WB = last ? Wo : WA+64*64;
    k_node<<<NB,256,SMN>>>(nw1+l*128*64,nb1+l*64,nw2+l*4096,nb2+l*64,WA,ba,WB,last,outp);
  }
}